// round 1
// baseline (speedup 1.0000x reference)
#include <cuda_runtime.h>
#include <cstdint>
#include <cstddef>

// Problem dims
#define BB 128
#define TT 64
#define EE 300
#define HH 2048
#define G4 8192          // 4*H
#define TOK 8192         // T*B

// Device scratch (allocation-free rule: static __device__ globals)
__device__ float g_Gih[(size_t)TOK * G4];   // 256 MB: precomputed x@W_ih^T + b_ih + b_hh
__device__ float g_h[2][BB * HH];           // double-buffered hidden state
__device__ float g_c[BB * HH];              // cell state

// ---------------------------------------------------------------------------
// tf32 helpers (mma.sync m16n8k8, row.col, fp32 accum)
// ---------------------------------------------------------------------------
__device__ __forceinline__ uint32_t f2tf(float f) {
    uint32_t u;
    asm("cvt.rna.tf32.f32 %0, %1;" : "=r"(u) : "f"(f));
    return u;
}

__device__ __forceinline__ void mma_tf32(float* d, const uint32_t* a, const uint32_t* b) {
    asm volatile(
        "mma.sync.aligned.m16n8k8.row.col.f32.tf32.tf32.f32 "
        "{%0,%1,%2,%3}, {%4,%5,%6,%7}, {%8,%9}, {%0,%1,%2,%3};\n"
        : "+f"(d[0]), "+f"(d[1]), "+f"(d[2]), "+f"(d[3])
        : "r"(a[0]), "r"(a[1]), "r"(a[2]), "r"(a[3]), "r"(b[0]), "r"(b[1]));
}

__device__ __forceinline__ float sigmoidf_(float x) {
    return 1.0f / (1.0f + expf(-x));
}

// ---------------------------------------------------------------------------
// init: zero h0 and c0 (must re-run every launch for graph determinism)
// ---------------------------------------------------------------------------
__global__ void init_kernel() {
    int i = blockIdx.x * blockDim.x + threadIdx.x;
    if (i < BB * HH) {
        g_h[0][i] = 0.0f;
        g_c[i]    = 0.0f;
    }
}

// ---------------------------------------------------------------------------
// Phase 1: G_ih[r][n] = embed[input[r]] @ W_ih^T + b_ih + b_hh
//   r = t*128 + b  (token index),  n in [0, 8192)
// CTA tile: 128 (tokens) x 128 (gate cols), K=300 padded to 320.
// 8 warps as 4(M) x 2(N); warp tile 32x64; mma m16n8k8 tf32.
// ---------------------------------------------------------------------------
__global__ __launch_bounds__(256) void phase1_kernel(
    const int*   __restrict__ input,
    const float* __restrict__ embed,
    const float* __restrict__ w_ih,
    const float* __restrict__ b_ih,
    const float* __restrict__ b_hh)
{
    __shared__ float sbuf[9216];   // As: [0,4608) = 128x36, Bs: [4608,9216) = 128x36
    __shared__ int   ids[128];
    float* As = sbuf;
    float* Bs = sbuf + 4608;

    const int tid  = threadIdx.x;
    const int lane = tid & 31;
    const int warp = tid >> 5;
    const int wm   = warp >> 1;    // 0..3
    const int wn   = warp & 1;     // 0..1
    const int g    = lane >> 2;    // groupID 0..7
    const int tg   = lane & 3;     // threadID_in_group 0..3

    const int n0 = blockIdx.x * 128;   // gate-col base
    const int r0 = blockIdx.y * 128;   // token-row base

    if (tid < 128) {
        int r = r0 + tid;
        int b = r & 127;
        int t = r >> 7;
        ids[tid] = input[b * TT + t];
    }

    float acc[2][8][4];
    #pragma unroll
    for (int mi = 0; mi < 2; mi++)
        #pragma unroll
        for (int ni = 0; ni < 8; ni++)
            #pragma unroll
            for (int e = 0; e < 4; e++) acc[mi][ni][e] = 0.0f;

    for (int kc = 0; kc < 320; kc += 32) {
        __syncthreads();
        // A tile: gathered embedding rows, 128x32, zero-padded past K=300
        #pragma unroll
        for (int p = 0; p < 4; p++) {
            int v   = p * 256 + tid;
            int row = v >> 3;
            int k4  = (v & 7) * 4;
            int kk  = kc + k4;
            float4 val = make_float4(0.f, 0.f, 0.f, 0.f);
            if (kk <= 296) {
                val = *reinterpret_cast<const float4*>(embed + (size_t)ids[row] * EE + kk);
            }
            *reinterpret_cast<float4*>(&As[row * 36 + k4]) = val;
        }
        // B tile: W_ih rows [n0, n0+128), 128x32
        #pragma unroll
        for (int p = 0; p < 4; p++) {
            int v   = p * 256 + tid;
            int row = v >> 3;
            int k4  = (v & 7) * 4;
            int kk  = kc + k4;
            float4 val = make_float4(0.f, 0.f, 0.f, 0.f);
            if (kk <= 296) {
                val = *reinterpret_cast<const float4*>(w_ih + (size_t)(n0 + row) * EE + kk);
            }
            *reinterpret_cast<float4*>(&Bs[row * 36 + k4]) = val;
        }
        __syncthreads();

        #pragma unroll
        for (int q = 0; q < 4; q++) {
            int kq = q * 8;
            uint32_t af[2][4];
            #pragma unroll
            for (int mi = 0; mi < 2; mi++) {
                int rb = wm * 32 + mi * 16;
                af[mi][0] = f2tf(As[(rb + g    ) * 36 + kq + tg    ]);
                af[mi][1] = f2tf(As[(rb + g + 8) * 36 + kq + tg    ]);
                af[mi][2] = f2tf(As[(rb + g    ) * 36 + kq + tg + 4]);
                af[mi][3] = f2tf(As[(rb + g + 8) * 36 + kq + tg + 4]);
            }
            uint32_t bf[8][2];
            #pragma unroll
            for (int ni = 0; ni < 8; ni++) {
                int cb = wn * 64 + ni * 8;
                bf[ni][0] = f2tf(Bs[(cb + g) * 36 + kq + tg    ]);
                bf[ni][1] = f2tf(Bs[(cb + g) * 36 + kq + tg + 4]);
            }
            #pragma unroll
            for (int mi = 0; mi < 2; mi++)
                #pragma unroll
                for (int ni = 0; ni < 8; ni++)
                    mma_tf32(acc[mi][ni], af[mi], bf[ni]);
        }
    }

    // Epilogue: + (b_ih + b_hh), write fp32 to g_Gih
    #pragma unroll
    for (int mi = 0; mi < 2; mi++) {
        #pragma unroll
        for (int ni = 0; ni < 8; ni++) {
            #pragma unroll
            for (int h2 = 0; h2 < 2; h2++) {
                int row = r0 + wm * 32 + mi * 16 + g + h2 * 8;
                int col = n0 + wn * 64 + ni * 8 + 2 * tg;
                float v0 = acc[mi][ni][h2 * 2 + 0] + b_ih[col]     + b_hh[col];
                float v1 = acc[mi][ni][h2 * 2 + 1] + b_ih[col + 1] + b_hh[col + 1];
                *reinterpret_cast<float2*>(&g_Gih[(size_t)row * G4 + col]) = make_float2(v0, v1);
            }
        }
    }
}

// ---------------------------------------------------------------------------
// Step t: gates = G_ih[t] + h @ W_hh^T ; fused LSTM cell update.
// CTA covers hidden cols [n0, n0+16), i.e. 64 gate-cols: 4 gates x 16.
// Grid 128 CTAs; 8 warps as 4(M) x 2(N); warp tile 32x32.
// B rows (local j in [0,64)): W_hh row = (j>>4)*2048 + n0 + (j&15).
// h double-buffered: in = g_h[t&1], out = g_h[(t+1)&1].
// ---------------------------------------------------------------------------
__global__ __launch_bounds__(256) void step_kernel(
    const float* __restrict__ w_hh,
    int t,
    float* __restrict__ d_out_opt)
{
    __shared__ float sbuf[9216];   // As: 128x36 = 4608 | Bs: 64x36 = 2304 ; epilogue Gs: 64x65
    float* As = sbuf;
    float* Bs = sbuf + 4608;
    float* Gs = sbuf;

    const float* __restrict__ h_in  = g_h[t & 1];
    float*       __restrict__ h_out = g_h[(t + 1) & 1];

    const int tid  = threadIdx.x;
    const int lane = tid & 31;
    const int warp = tid >> 5;
    const int wm   = warp >> 1;    // 0..3
    const int wn   = warp & 1;     // 0..1
    const int g    = lane >> 2;
    const int tg   = lane & 3;

    const int n0 = blockIdx.x * 16;   // hidden-col base (128 CTAs)

    float acc[2][4][4];
    #pragma unroll
    for (int mi = 0; mi < 2; mi++)
        #pragma unroll
        for (int ni = 0; ni < 4; ni++)
            #pragma unroll
            for (int e = 0; e < 4; e++) acc[mi][ni][e] = 0.0f;

    for (int kc = 0; kc < HH; kc += 32) {
        __syncthreads();
        // A tile: h_in 128x32
        #pragma unroll
        for (int p = 0; p < 4; p++) {
            int v   = p * 256 + tid;
            int row = v >> 3;
            int k4  = (v & 7) * 4;
            float4 val = *reinterpret_cast<const float4*>(h_in + (size_t)row * HH + kc + k4);
            *reinterpret_cast<float4*>(&As[row * 36 + k4]) = val;
        }
        // B tile: 64 W_hh rows x 32
        #pragma unroll
        for (int p = 0; p < 2; p++) {
            int v   = p * 256 + tid;
            int j   = v >> 3;
            int k4  = (v & 7) * 4;
            int wrow = (j >> 4) * HH + n0 + (j & 15);
            float4 val = *reinterpret_cast<const float4*>(w_hh + (size_t)wrow * HH + kc + k4);
            *reinterpret_cast<float4*>(&Bs[j * 36 + k4]) = val;
        }
        __syncthreads();

        #pragma unroll
        for (int q = 0; q < 4; q++) {
            int kq = q * 8;
            uint32_t af[2][4];
            #pragma unroll
            for (int mi = 0; mi < 2; mi++) {
                int rb = wm * 32 + mi * 16;
                af[mi][0] = f2tf(As[(rb + g    ) * 36 + kq + tg    ]);
                af[mi][1] = f2tf(As[(rb + g + 8) * 36 + kq + tg    ]);
                af[mi][2] = f2tf(As[(rb + g    ) * 36 + kq + tg + 4]);
                af[mi][3] = f2tf(As[(rb + g + 8) * 36 + kq + tg + 4]);
            }
            uint32_t bf[4][2];
            #pragma unroll
            for (int ni = 0; ni < 4; ni++) {
                int cb = wn * 32 + ni * 8;
                bf[ni][0] = f2tf(Bs[(cb + g) * 36 + kq + tg    ]);
                bf[ni][1] = f2tf(Bs[(cb + g) * 36 + kq + tg + 4]);
            }
            #pragma unroll
            for (int mi = 0; mi < 2; mi++)
                #pragma unroll
                for (int ni = 0; ni < 4; ni++)
                    mma_tf32(acc[mi][ni], af[mi], bf[ni]);
        }
    }

    // Epilogue: two row-halves (64 rows each) through smem, fused LSTM update
    #pragma unroll
    for (int half = 0; half < 2; half++) {
        __syncthreads();
        if ((wm >> 1) == half) {
            #pragma unroll
            for (int mi = 0; mi < 2; mi++) {
                #pragma unroll
                for (int ni = 0; ni < 4; ni++) {
                    #pragma unroll
                    for (int h2 = 0; h2 < 2; h2++) {
                        int rloc = (wm & 1) * 32 + mi * 16 + g + h2 * 8;
                        int col  = wn * 32 + ni * 8 + 2 * tg;
                        Gs[rloc * 65 + col]     = acc[mi][ni][h2 * 2 + 0];
                        Gs[rloc * 65 + col + 1] = acc[mi][ni][h2 * 2 + 1];
                    }
                }
            }
        }
        __syncthreads();
        // 64 rows x 16 hidden cols = 1024 elems, 4 per thread
        #pragma unroll
        for (int p = 0; p < 4; p++) {
            int idx = p * 256 + tid;
            int c   = idx & 15;
            int bl  = idx >> 4;          // 0..63
            int b   = half * 64 + bl;    // batch row
            size_t gbase = ((size_t)(t * BB + b)) * G4 + n0;

            float iv = Gs[bl * 65 +  0 + c] + g_Gih[gbase +    0 + c];
            float fv = Gs[bl * 65 + 16 + c] + g_Gih[gbase + 2048 + c];
            float gv = Gs[bl * 65 + 32 + c] + g_Gih[gbase + 4096 + c];
            float ov = Gs[bl * 65 + 48 + c] + g_Gih[gbase + 6144 + c];

            float ig = sigmoidf_(iv);
            float fg = sigmoidf_(fv);
            float gg = tanhf(gv);
            float og = sigmoidf_(ov);

            int hcol = n0 + c;
            float cold = g_c[b * HH + hcol];
            float cn = fg * cold + ig * gg;
            g_c[b * HH + hcol] = cn;
            float hn = og * tanhf(cn);
            h_out[b * HH + hcol] = hn;
            if (d_out_opt) d_out_opt[b * HH + hcol] = hn;
        }
    }
}

// ---------------------------------------------------------------------------
extern "C" void kernel_launch(void* const* d_in, const int* in_sizes, int n_in,
                              void* d_out, int out_size) {
    (void)in_sizes; (void)n_in; (void)out_size;
    const int*   input = (const int*)  d_in[0];
    const float* embed = (const float*)d_in[1];
    const float* w_ih  = (const float*)d_in[2];
    const float* w_hh  = (const float*)d_in[3];
    const float* b_ih  = (const float*)d_in[4];
    const float* b_hh  = (const float*)d_in[5];
    float* out = (float*)d_out;

    init_kernel<<<(BB * HH + 255) / 256, 256>>>();
    phase1_kernel<<<dim3(64, 64), 256>>>(input, embed, w_ih, b_ih, b_hh);
    for (int t = 0; t < TT; t++) {
        step_kernel<<<128, 256>>>(w_hh, t, (t == TT - 1) ? out : nullptr);
    }
}

// round 2
// speedup vs baseline: 1.7465x; 1.7465x over previous
#include <cuda_runtime.h>
#include <cstdint>
#include <cstddef>

// Problem dims
#define BB 128
#define TT 64
#define EE 300
#define HH 2048
#define G4 8192          // 4*H
#define TOK 8192         // T*B

// Packed-chunk geometry for the recurrent GEMM
#define CHUNK 64                     // K elements per pipeline stage
#define NCHUNK (HH / CHUNK)          // 32
#define A_CH_FLOATS (BB * CHUNK)     // 8192 floats per A chunk (32KB)
#define B_CH_FLOATS (64 * CHUNK)     // 4096 floats per B chunk (16KB)
#define STAGE_FLOATS (A_CH_FLOATS + B_CH_FLOATS)  // 12288
#define NSTAGE 3
#define SMEM_BYTES (NSTAGE * STAGE_FLOATS * 4)    // 147456

// Device scratch (allocation-free rule: static __device__ globals)
__device__ float g_Gih[(size_t)TOK * G4];            // 256 MB, layout ((t*128+cta)*128+b)*64 + gate*16 + c
__device__ float g_Wpack[(size_t)128 * NCHUNK * B_CH_FLOATS]; // 64 MB tf32-rounded, fragment-packed
__device__ float g_hpack[2][BB * HH];                // fragment-packed, tf32-rounded hidden state
__device__ float g_c[BB * HH];                       // cell state (fp32, plain [b][h])

// ---------------------------------------------------------------------------
__device__ __forceinline__ uint32_t f2tf(float f) {
    uint32_t u;
    asm("cvt.rna.tf32.f32 %0, %1;" : "=r"(u) : "f"(f));
    return u;
}

__device__ __forceinline__ void mma_tf32(float* d, uint32_t a0, uint32_t a1, uint32_t a2, uint32_t a3,
                                         uint32_t b0, uint32_t b1) {
    asm volatile(
        "mma.sync.aligned.m16n8k8.row.col.f32.tf32.tf32.f32 "
        "{%0,%1,%2,%3}, {%4,%5,%6,%7}, {%8,%9}, {%0,%1,%2,%3};\n"
        : "+f"(d[0]), "+f"(d[1]), "+f"(d[2]), "+f"(d[3])
        : "r"(a0), "r"(a1), "r"(a2), "r"(a3), "r"(b0), "r"(b1));
}

__device__ __forceinline__ void cp16(float* s, const float* g) {
    uint32_t sa = (uint32_t)__cvta_generic_to_shared(s);
    asm volatile("cp.async.cg.shared.global [%0], [%1], 16;\n" :: "r"(sa), "l"(g));
}
#define CP_COMMIT() asm volatile("cp.async.commit_group;\n" ::: "memory")
#define CP_WAIT(N)  asm volatile("cp.async.wait_group %0;\n" :: "n"(N) : "memory")

__device__ __forceinline__ float sigmoidf_(float x) {
    return 1.0f / (1.0f + __expf(-x));
}

// ---------------------------------------------------------------------------
// init: zero h0 (packed) and c0
// ---------------------------------------------------------------------------
__global__ void init_kernel() {
    int i = blockIdx.x * blockDim.x + threadIdx.x;
    if (i < BB * HH) {
        g_hpack[0][i] = 0.0f;
        g_c[i]        = 0.0f;
    }
}

// ---------------------------------------------------------------------------
// Pack W_hh into tf32-rounded, B-fragment order.
// Layout: [cta 128][kc 32][q 8][pair 4][lane 32][slot 4]
//   slot = which*2 + khalf, which selects n-tile (pair*2+which), khalf selects k vs k+4
//   B-frag (8k x 8n tile): b0 = (k=tg, n=g), b1 = (k=tg+4, n=g)
//   CTA column j (0..63): gate = j>>4, hidden = cta*16 + (j&15); W row = gate*2048 + hidden
// One thread per float4 (coalesced stores).
// ---------------------------------------------------------------------------
__global__ __launch_bounds__(256) void pack_w_kernel(const float* __restrict__ w_hh) {
    int p4 = blockIdx.x * blockDim.x + threadIdx.x;   // 0 .. 4194303
    int lane = p4 & 31;  int rest = p4 >> 5;
    int pair = rest & 3; rest >>= 2;
    int q    = rest & 7; rest >>= 3;
    int kc   = rest & 31;
    int cta  = rest >> 5;
    int g  = lane >> 2;
    int tg = lane & 3;

    float4 v;
    float* vv = (float*)&v;
    #pragma unroll
    for (int which = 0; which < 2; which++) {
        int j = (pair * 2 + which) * 8 + g;
        int wrow = (j >> 4) * HH + cta * 16 + (j & 15);
        #pragma unroll
        for (int khalf = 0; khalf < 2; khalf++) {
            int k = kc * CHUNK + q * 8 + khalf * 4 + tg;
            float x = w_hh[(size_t)wrow * HH + k];
            vv[which * 2 + khalf] = __uint_as_float(f2tf(x));
        }
    }
    *reinterpret_cast<float4*>(&g_Wpack[(size_t)p4 * 4]) = v;
}

// ---------------------------------------------------------------------------
// Phase 1: G_ih[r][N] = embed[input[r]] @ W_ih^T + b_ih + b_hh
// Written into the per-CTA-contiguous layout used by step_kernel's epilogue.
// ---------------------------------------------------------------------------
__global__ __launch_bounds__(256) void phase1_kernel(
    const int*   __restrict__ input,
    const float* __restrict__ embed,
    const float* __restrict__ w_ih,
    const float* __restrict__ b_ih,
    const float* __restrict__ b_hh)
{
    __shared__ float sbuf[9216];   // As: 128x36, Bs: 128x36
    __shared__ int   ids[128];
    float* As = sbuf;
    float* Bs = sbuf + 4608;

    const int tid  = threadIdx.x;
    const int lane = tid & 31;
    const int warp = tid >> 5;
    const int wm   = warp >> 1;
    const int wn   = warp & 1;
    const int g    = lane >> 2;
    const int tg   = lane & 3;

    const int n0 = blockIdx.x * 128;
    const int r0 = blockIdx.y * 128;

    if (tid < 128) {
        int r = r0 + tid;
        int b = r & 127;
        int t = r >> 7;
        ids[tid] = input[b * TT + t];
    }

    float acc[2][8][4];
    #pragma unroll
    for (int mi = 0; mi < 2; mi++)
        #pragma unroll
        for (int ni = 0; ni < 8; ni++)
            #pragma unroll
            for (int e = 0; e < 4; e++) acc[mi][ni][e] = 0.0f;

    for (int kc = 0; kc < 320; kc += 32) {
        __syncthreads();
        #pragma unroll
        for (int p = 0; p < 4; p++) {
            int v   = p * 256 + tid;
            int row = v >> 3;
            int k4  = (v & 7) * 4;
            int kk  = kc + k4;
            float4 val = make_float4(0.f, 0.f, 0.f, 0.f);
            if (kk <= 296) {
                val = *reinterpret_cast<const float4*>(embed + (size_t)ids[row] * EE + kk);
            }
            *reinterpret_cast<float4*>(&As[row * 36 + k4]) = val;
        }
        #pragma unroll
        for (int p = 0; p < 4; p++) {
            int v   = p * 256 + tid;
            int row = v >> 3;
            int k4  = (v & 7) * 4;
            int kk  = kc + k4;
            float4 val = make_float4(0.f, 0.f, 0.f, 0.f);
            if (kk <= 296) {
                val = *reinterpret_cast<const float4*>(w_ih + (size_t)(n0 + row) * EE + kk);
            }
            *reinterpret_cast<float4*>(&Bs[row * 36 + k4]) = val;
        }
        __syncthreads();

        #pragma unroll
        for (int q = 0; q < 4; q++) {
            int kq = q * 8;
            uint32_t af[2][4];
            #pragma unroll
            for (int mi = 0; mi < 2; mi++) {
                int rb = wm * 32 + mi * 16;
                af[mi][0] = f2tf(As[(rb + g    ) * 36 + kq + tg    ]);
                af[mi][1] = f2tf(As[(rb + g + 8) * 36 + kq + tg    ]);
                af[mi][2] = f2tf(As[(rb + g    ) * 36 + kq + tg + 4]);
                af[mi][3] = f2tf(As[(rb + g + 8) * 36 + kq + tg + 4]);
            }
            uint32_t bf[8][2];
            #pragma unroll
            for (int ni = 0; ni < 8; ni++) {
                int cb = wn * 64 + ni * 8;
                bf[ni][0] = f2tf(Bs[(cb + g) * 36 + kq + tg    ]);
                bf[ni][1] = f2tf(Bs[(cb + g) * 36 + kq + tg + 4]);
            }
            #pragma unroll
            for (int mi = 0; mi < 2; mi++)
                #pragma unroll
                for (int ni = 0; ni < 8; ni++)
                    mma_tf32(acc[mi][ni], af[mi][0], af[mi][1], af[mi][2], af[mi][3],
                             bf[ni][0], bf[ni][1]);
        }
    }

    // Epilogue: + (b_ih + b_hh), write into step-friendly layout
    #pragma unroll
    for (int mi = 0; mi < 2; mi++) {
        #pragma unroll
        for (int ni = 0; ni < 8; ni++) {
            #pragma unroll
            for (int h2 = 0; h2 < 2; h2++) {
                int row = r0 + wm * 32 + mi * 16 + g + h2 * 8;
                int t = row >> 7;
                int b = row & 127;
                int col = n0 + wn * 64 + ni * 8 + 2 * tg;
                int cta = (col & (HH - 1)) >> 4;
                int j   = (col >> 11) * 16 + (col & 15);
                float v0 = acc[mi][ni][h2 * 2 + 0] + b_ih[col]     + b_hh[col];
                float v1 = acc[mi][ni][h2 * 2 + 1] + b_ih[col + 1] + b_hh[col + 1];
                size_t addr = ((size_t)(t * 128 + cta) * 128 + b) * 64 + j;
                *reinterpret_cast<float2*>(&g_Gih[addr]) = make_float2(v0, v1);
            }
        }
    }
}

// ---------------------------------------------------------------------------
// Step t: gates = G_ih[t] + h @ W_hh^T ; fused LSTM cell update.
// 128 CTAs, 256 threads (8 warps as 4M x 2N, warp tile 32x32).
// All operands pre-packed in fragment order; cp.async 3-stage pipeline.
// A-pack layout: [kc][q 8][m_tile 8][lane 32][slot 4]
//   slot = khalf*2 + rowhigh; A-frag: a0=(g,tg) a1=(g+8,tg) a2=(g,tg+4) a3=(g+8,tg+4)
// ---------------------------------------------------------------------------
__global__ __launch_bounds__(256) void step_kernel(int t, float* __restrict__ d_out_opt)
{
    extern __shared__ float smem[];

    const float* __restrict__ h_in  = g_hpack[t & 1];
    float*       __restrict__ h_out = g_hpack[(t + 1) & 1];

    const int tid  = threadIdx.x;
    const int lane = tid & 31;
    const int warp = tid >> 5;
    const int wm   = warp >> 1;    // 0..3
    const int wn   = warp & 1;     // 0..1
    const int g    = lane >> 2;
    const int tg   = lane & 3;
    const int cta  = blockIdx.x;

    const float* __restrict__ wb = g_Wpack + (size_t)cta * (NCHUNK * B_CH_FLOATS);

    // ---- stage loader ----
    auto load_stage = [&](int s, int kc) {
        float* dst = smem + s * STAGE_FLOATS;
        const float* ga = h_in + (size_t)kc * A_CH_FLOATS;
        const float* gb = wb + (size_t)kc * B_CH_FLOATS;
        #pragma unroll
        for (int i = 0; i < A_CH_FLOATS / (256 * 4); i++)   // 8
            cp16(dst + (i * 256 + tid) * 4, ga + (i * 256 + tid) * 4);
        #pragma unroll
        for (int i = 0; i < B_CH_FLOATS / (256 * 4); i++)   // 4
            cp16(dst + A_CH_FLOATS + (i * 256 + tid) * 4, gb + (i * 256 + tid) * 4);
    };

    load_stage(0, 0); CP_COMMIT();
    load_stage(1, 1); CP_COMMIT();

    float acc[2][4][4];
    #pragma unroll
    for (int mi = 0; mi < 2; mi++)
        #pragma unroll
        for (int ni = 0; ni < 4; ni++)
            #pragma unroll
            for (int e = 0; e < 4; e++) acc[mi][ni][e] = 0.0f;

    for (int kc = 0; kc < NCHUNK; kc++) {
        CP_WAIT(1);
        __syncthreads();
        if (kc + 2 < NCHUNK) load_stage((kc + 2) % NSTAGE, kc + 2);
        CP_COMMIT();

        const float* S = smem + (kc % NSTAGE) * STAGE_FLOATS;
        const float* SA = S + lane * 4;
        const float* SB = S + A_CH_FLOATS + lane * 4;

        #pragma unroll
        for (int q = 0; q < 8; q++) {
            float4 a0 = *reinterpret_cast<const float4*>(SA + (q * 8 + wm * 2 + 0) * 128);
            float4 a1 = *reinterpret_cast<const float4*>(SA + (q * 8 + wm * 2 + 1) * 128);
            float4 bA = *reinterpret_cast<const float4*>(SB + (q * 4 + wn * 2 + 0) * 128);
            float4 bB = *reinterpret_cast<const float4*>(SB + (q * 4 + wn * 2 + 1) * 128);

            uint32_t a0x = __float_as_uint(a0.x), a0y = __float_as_uint(a0.y),
                     a0z = __float_as_uint(a0.z), a0w = __float_as_uint(a0.w);
            uint32_t a1x = __float_as_uint(a1.x), a1y = __float_as_uint(a1.y),
                     a1z = __float_as_uint(a1.z), a1w = __float_as_uint(a1.w);

            mma_tf32(acc[0][0], a0x, a0y, a0z, a0w, __float_as_uint(bA.x), __float_as_uint(bA.y));
            mma_tf32(acc[1][0], a1x, a1y, a1z, a1w, __float_as_uint(bA.x), __float_as_uint(bA.y));
            mma_tf32(acc[0][1], a0x, a0y, a0z, a0w, __float_as_uint(bA.z), __float_as_uint(bA.w));
            mma_tf32(acc[1][1], a1x, a1y, a1z, a1w, __float_as_uint(bA.z), __float_as_uint(bA.w));
            mma_tf32(acc[0][2], a0x, a0y, a0z, a0w, __float_as_uint(bB.x), __float_as_uint(bB.y));
            mma_tf32(acc[1][2], a1x, a1y, a1z, a1w, __float_as_uint(bB.x), __float_as_uint(bB.y));
            mma_tf32(acc[0][3], a0x, a0y, a0z, a0w, __float_as_uint(bB.z), __float_as_uint(bB.w));
            mma_tf32(acc[1][3], a1x, a1y, a1z, a1w, __float_as_uint(bB.z), __float_as_uint(bB.w));
        }
    }

    // ---- epilogue: route acc through smem (reuse stage memory), fused LSTM ----
    __syncthreads();
    float* Gs = smem;                       // [128][68]
    #pragma unroll
    for (int mi = 0; mi < 2; mi++) {
        #pragma unroll
        for (int ni = 0; ni < 4; ni++) {
            #pragma unroll
            for (int rh = 0; rh < 2; rh++) {
                int row = wm * 32 + mi * 16 + g + rh * 8;
                int col = wn * 32 + ni * 8 + 2 * tg;
                *reinterpret_cast<float2*>(&Gs[row * 68 + col]) =
                    make_float2(acc[mi][ni][rh * 2 + 0], acc[mi][ni][rh * 2 + 1]);
            }
        }
    }
    __syncthreads();

    const float* __restrict__ gih = g_Gih + ((size_t)(t * 128 + cta) * 128) * 64;
    const int n0 = cta * 16;

    #pragma unroll
    for (int p = 0; p < 8; p++) {
        int idx = p * 256 + tid;
        int c   = idx & 15;
        int b   = idx >> 4;
        const float* base = gih + b * 64;

        float iv = Gs[b * 68 +      c] + base[     c];
        float fv = Gs[b * 68 + 16 + c] + base[16 + c];
        float gv = Gs[b * 68 + 32 + c] + base[32 + c];
        float ov = Gs[b * 68 + 48 + c] + base[48 + c];

        float ig = sigmoidf_(iv);
        float fg = sigmoidf_(fv);
        float gg = tanhf(gv);
        float og = sigmoidf_(ov);

        int hcol = n0 + c;
        float cold = g_c[b * HH + hcol];
        float cn = fg * cold + ig * gg;
        g_c[b * HH + hcol] = cn;
        float hn = og * tanhf(cn);

        // packed store for the next step's A operand (tf32-rounded)
        int kc2   = hcol >> 6;
        int q2    = (hcol >> 3) & 7;
        int tg2   = hcol & 3;
        int khalf = (hcol >> 2) & 1;
        int mt    = b >> 4;
        int g2    = b & 7;
        int rh    = (b >> 3) & 1;
        int lane2 = g2 * 4 + tg2;
        int slot  = khalf * 2 + rh;
        h_out[((kc2 * 8 + q2) * 8 + mt) * 128 + lane2 * 4 + slot] = __uint_as_float(f2tf(hn));

        if (d_out_opt) d_out_opt[b * HH + hcol] = hn;
    }
}

// ---------------------------------------------------------------------------
extern "C" void kernel_launch(void* const* d_in, const int* in_sizes, int n_in,
                              void* d_out, int out_size) {
    (void)in_sizes; (void)n_in; (void)out_size;
    const int*   input = (const int*)  d_in[0];
    const float* embed = (const float*)d_in[1];
    const float* w_ih  = (const float*)d_in[2];
    const float* w_hh  = (const float*)d_in[3];
    const float* b_ih  = (const float*)d_in[4];
    const float* b_hh  = (const float*)d_in[5];
    float* out = (float*)d_out;

    static int smem_set = 0;
    if (!smem_set) {
        cudaFuncSetAttribute(step_kernel, cudaFuncAttributeMaxDynamicSharedMemorySize, SMEM_BYTES);
        smem_set = 1;
    }

    init_kernel<<<(BB * HH + 255) / 256, 256>>>();
    pack_w_kernel<<<16384, 256>>>(w_hh);
    phase1_kernel<<<dim3(64, 64), 256>>>(input, embed, w_ih, b_ih, b_hh);
    for (int t = 0; t < TT; t++) {
        step_kernel<<<128, 256, SMEM_BYTES>>>(t, (t == TT - 1) ? out : nullptr);
    }
}

// round 5
// speedup vs baseline: 1.7877x; 1.0236x over previous
#include <cuda_runtime.h>
#include <cstdint>
#include <cstddef>

// Problem dims
#define BB 128
#define TT 64
#define EE 300
#define HH 2048
#define G4 8192          // 4*H
#define TOK 8192         // T*B

// Packed-chunk geometry for the recurrent GEMM
#define CHUNK 64                     // K elements per pipeline stage
#define NCHUNK (HH / CHUNK)          // 32
#define A_CH_FLOATS (BB * CHUNK)     // 8192 floats per A chunk (32KB)
#define B_CH_FLOATS (64 * CHUNK)     // 4096 floats per B chunk (16KB)
#define STAGE_FLOATS (A_CH_FLOATS + B_CH_FLOATS)  // 12288
#define NSTAGE 4
#define SMEM_BYTES (NSTAGE * STAGE_FLOATS * 4)    // 196608

// Device scratch (allocation-free rule: static __device__ globals)
__device__ float g_Gih[(size_t)TOK * G4];            // 256 MB, layout ((t*128+cta)*128+b)*64 + gate*16 + c
__device__ float g_Wpack[(size_t)128 * NCHUNK * B_CH_FLOATS]; // 64 MB tf32-rounded, fragment-packed
__device__ float g_hpack[2][BB * HH];                // fragment-packed, tf32-rounded hidden state
__device__ float g_c[BB * HH];                       // cell state (fp32, plain [b][h])

// ---------------------------------------------------------------------------
__device__ __forceinline__ uint32_t f2tf(float f) {
    uint32_t u;
    asm("cvt.rna.tf32.f32 %0, %1;" : "=r"(u) : "f"(f));
    return u;
}

__device__ __forceinline__ void mma_tf32(float* d, uint32_t a0, uint32_t a1, uint32_t a2, uint32_t a3,
                                         uint32_t b0, uint32_t b1) {
    asm volatile(
        "mma.sync.aligned.m16n8k8.row.col.f32.tf32.tf32.f32 "
        "{%0,%1,%2,%3}, {%4,%5,%6,%7}, {%8,%9}, {%0,%1,%2,%3};\n"
        : "+f"(d[0]), "+f"(d[1]), "+f"(d[2]), "+f"(d[3])
        : "r"(a0), "r"(a1), "r"(a2), "r"(a3), "r"(b0), "r"(b1));
}

__device__ __forceinline__ void cp16(float* s, const float* g) {
    uint32_t sa = (uint32_t)__cvta_generic_to_shared(s);
    asm volatile("cp.async.cg.shared.global [%0], [%1], 16;\n" :: "r"(sa), "l"(g));
}
#define CP_COMMIT() asm volatile("cp.async.commit_group;\n" ::: "memory")
#define CP_WAIT(N)  asm volatile("cp.async.wait_group %0;\n" :: "n"(N) : "memory")

__device__ __forceinline__ float sigmoidf_(float x) {
    return 1.0f / (1.0f + __expf(-x));
}

// ---------------------------------------------------------------------------
// init: zero h0 (packed) and c0
// ---------------------------------------------------------------------------
__global__ void init_kernel() {
    int i = blockIdx.x * blockDim.x + threadIdx.x;
    if (i < BB * HH) {
        g_hpack[0][i] = 0.0f;
        g_c[i]        = 0.0f;
    }
}

// ---------------------------------------------------------------------------
// Pack W_hh into tf32-rounded, B-fragment order.
// Layout: [cta 128][kc 32][q 8][pair 4][lane 32][slot 4]
// ---------------------------------------------------------------------------
__global__ __launch_bounds__(256) void pack_w_kernel(const float* __restrict__ w_hh) {
    int p4 = blockIdx.x * blockDim.x + threadIdx.x;   // 0 .. 4194303
    int lane = p4 & 31;  int rest = p4 >> 5;
    int pair = rest & 3; rest >>= 2;
    int q    = rest & 7; rest >>= 3;
    int kc   = rest & 31;
    int cta  = rest >> 5;
    int g  = lane >> 2;
    int tg = lane & 3;

    float4 v;
    float* vv = (float*)&v;
    #pragma unroll
    for (int which = 0; which < 2; which++) {
        int j = (pair * 2 + which) * 8 + g;
        int wrow = (j >> 4) * HH + cta * 16 + (j & 15);
        #pragma unroll
        for (int khalf = 0; khalf < 2; khalf++) {
            int k = kc * CHUNK + q * 8 + khalf * 4 + tg;
            float x = w_hh[(size_t)wrow * HH + k];
            vv[which * 2 + khalf] = __uint_as_float(f2tf(x));
        }
    }
    *reinterpret_cast<float4*>(&g_Wpack[(size_t)p4 * 4]) = v;
}

// ---------------------------------------------------------------------------
// Phase 1: G_ih[r][N] = embed[input[r]] @ W_ih^T + b_ih + b_hh
// ---------------------------------------------------------------------------
__global__ __launch_bounds__(256) void phase1_kernel(
    const int*   __restrict__ input,
    const float* __restrict__ embed,
    const float* __restrict__ w_ih,
    const float* __restrict__ b_ih,
    const float* __restrict__ b_hh)
{
    __shared__ float sbuf[9216];   // As: 128x36, Bs: 128x36
    __shared__ int   ids[128];
    float* As = sbuf;
    float* Bs = sbuf + 4608;

    const int tid  = threadIdx.x;
    const int lane = tid & 31;
    const int warp = tid >> 5;
    const int wm   = warp >> 1;
    const int wn   = warp & 1;
    const int g    = lane >> 2;
    const int tg   = lane & 3;

    const int n0 = blockIdx.x * 128;
    const int r0 = blockIdx.y * 128;

    if (tid < 128) {
        int r = r0 + tid;
        int b = r & 127;
        int t = r >> 7;
        ids[tid] = input[b * TT + t];
    }

    float acc[2][8][4];
    #pragma unroll
    for (int mi = 0; mi < 2; mi++)
        #pragma unroll
        for (int ni = 0; ni < 8; ni++)
            #pragma unroll
            for (int e = 0; e < 4; e++) acc[mi][ni][e] = 0.0f;

    for (int kc = 0; kc < 320; kc += 32) {
        __syncthreads();
        #pragma unroll
        for (int p = 0; p < 4; p++) {
            int v   = p * 256 + tid;
            int row = v >> 3;
            int k4  = (v & 7) * 4;
            int kk  = kc + k4;
            float4 val = make_float4(0.f, 0.f, 0.f, 0.f);
            if (kk <= 296) {
                val = *reinterpret_cast<const float4*>(embed + (size_t)ids[row] * EE + kk);
            }
            *reinterpret_cast<float4*>(&As[row * 36 + k4]) = val;
        }
        #pragma unroll
        for (int p = 0; p < 4; p++) {
            int v   = p * 256 + tid;
            int row = v >> 3;
            int k4  = (v & 7) * 4;
            int kk  = kc + k4;
            float4 val = make_float4(0.f, 0.f, 0.f, 0.f);
            if (kk <= 296) {
                val = *reinterpret_cast<const float4*>(w_ih + (size_t)(n0 + row) * EE + kk);
            }
            *reinterpret_cast<float4*>(&Bs[row * 36 + k4]) = val;
        }
        __syncthreads();

        #pragma unroll
        for (int q = 0; q < 4; q++) {
            int kq = q * 8;
            uint32_t af[2][4];
            #pragma unroll
            for (int mi = 0; mi < 2; mi++) {
                int rb = wm * 32 + mi * 16;
                af[mi][0] = f2tf(As[(rb + g    ) * 36 + kq + tg    ]);
                af[mi][1] = f2tf(As[(rb + g + 8) * 36 + kq + tg    ]);
                af[mi][2] = f2tf(As[(rb + g    ) * 36 + kq + tg + 4]);
                af[mi][3] = f2tf(As[(rb + g + 8) * 36 + kq + tg + 4]);
            }
            uint32_t bf[8][2];
            #pragma unroll
            for (int ni = 0; ni < 8; ni++) {
                int cb = wn * 64 + ni * 8;
                bf[ni][0] = f2tf(Bs[(cb + g) * 36 + kq + tg    ]);
                bf[ni][1] = f2tf(Bs[(cb + g) * 36 + kq + tg + 4]);
            }
            #pragma unroll
            for (int mi = 0; mi < 2; mi++)
                #pragma unroll
                for (int ni = 0; ni < 8; ni++)
                    mma_tf32(acc[mi][ni], af[mi][0], af[mi][1], af[mi][2], af[mi][3],
                             bf[ni][0], bf[ni][1]);
        }
    }

    #pragma unroll
    for (int mi = 0; mi < 2; mi++) {
        #pragma unroll
        for (int ni = 0; ni < 8; ni++) {
            #pragma unroll
            for (int h2 = 0; h2 < 2; h2++) {
                int row = r0 + wm * 32 + mi * 16 + g + h2 * 8;
                int t = row >> 7;
                int b = row & 127;
                int col = n0 + wn * 64 + ni * 8 + 2 * tg;
                int cta = (col & (HH - 1)) >> 4;
                int j   = (col >> 11) * 16 + (col & 15);
                float v0 = acc[mi][ni][h2 * 2 + 0] + b_ih[col]     + b_hh[col];
                float v1 = acc[mi][ni][h2 * 2 + 1] + b_ih[col + 1] + b_hh[col + 1];
                size_t addr = ((size_t)(t * 128 + cta) * 128 + b) * 64 + j;
                *reinterpret_cast<float2*>(&g_Gih[addr]) = make_float2(v0, v1);
            }
        }
    }
}

// ---------------------------------------------------------------------------
// Step t: gates = G_ih[t] + h @ W_hh^T ; fused LSTM cell update.
// 128 CTAs, 256 threads (8 warps as 4M x 2N, warp tile 32x32).
// 4-stage cp.async pipeline (wait_group 2) + register double-buffered frags.
// ---------------------------------------------------------------------------
__global__ __launch_bounds__(256) void step_kernel(int t, float* __restrict__ d_out_opt)
{
    extern __shared__ float smem[];

    const float* __restrict__ h_in  = g_hpack[t & 1];
    float*       __restrict__ h_out = g_hpack[(t + 1) & 1];

    const int tid  = threadIdx.x;
    const int lane = tid & 31;
    const int warp = tid >> 5;
    const int wm   = warp >> 1;    // 0..3
    const int wn   = warp & 1;     // 0..1
    const int g    = lane >> 2;
    const int tg   = lane & 3;
    const int cta  = blockIdx.x;

    const float* __restrict__ wb = g_Wpack + (size_t)cta * (NCHUNK * B_CH_FLOATS);

    auto load_stage = [&](int s, int kc) {
        float* dst = smem + s * STAGE_FLOATS;
        const float* ga = h_in + (size_t)kc * A_CH_FLOATS;
        const float* gb = wb + (size_t)kc * B_CH_FLOATS;
        #pragma unroll
        for (int i = 0; i < A_CH_FLOATS / (256 * 4); i++)   // 8
            cp16(dst + (i * 256 + tid) * 4, ga + (i * 256 + tid) * 4);
        #pragma unroll
        for (int i = 0; i < B_CH_FLOATS / (256 * 4); i++)   // 4
            cp16(dst + A_CH_FLOATS + (i * 256 + tid) * 4, gb + (i * 256 + tid) * 4);
    };

    load_stage(0, 0); CP_COMMIT();
    load_stage(1, 1); CP_COMMIT();
    load_stage(2, 2); CP_COMMIT();

    float acc[2][4][4];
    #pragma unroll
    for (int mi = 0; mi < 2; mi++)
        #pragma unroll
        for (int ni = 0; ni < 4; ni++)
            #pragma unroll
            for (int e = 0; e < 4; e++) acc[mi][ni][e] = 0.0f;

    for (int kc = 0; kc < NCHUNK; kc++) {
        CP_WAIT(2);
        __syncthreads();
        if (kc + 3 < NCHUNK) load_stage((kc + 3) & 3, kc + 3);
        CP_COMMIT();

        const float* S = smem + (kc & 3) * STAGE_FLOATS;
        const float* SA = S + lane * 4;
        const float* SB = S + A_CH_FLOATS + lane * 4;

        // register double-buffered fragments over the 8 q-iterations
        float4 a0 = *reinterpret_cast<const float4*>(SA + (wm * 2 + 0) * 128);
        float4 a1 = *reinterpret_cast<const float4*>(SA + (wm * 2 + 1) * 128);
        float4 bA = *reinterpret_cast<const float4*>(SB + (wn * 2 + 0) * 128);
        float4 bB = *reinterpret_cast<const float4*>(SB + (wn * 2 + 1) * 128);

        #pragma unroll
        for (int q = 0; q < 8; q++) {
            float4 na0, na1, nbA, nbB;
            if (q < 7) {
                na0 = *reinterpret_cast<const float4*>(SA + ((q + 1) * 8 + wm * 2 + 0) * 128);
                na1 = *reinterpret_cast<const float4*>(SA + ((q + 1) * 8 + wm * 2 + 1) * 128);
                nbA = *reinterpret_cast<const float4*>(SB + ((q + 1) * 4 + wn * 2 + 0) * 128);
                nbB = *reinterpret_cast<const float4*>(SB + ((q + 1) * 4 + wn * 2 + 1) * 128);
            }

            uint32_t a0x = __float_as_uint(a0.x), a0y = __float_as_uint(a0.y),
                     a0z = __float_as_uint(a0.z), a0w = __float_as_uint(a0.w);
            uint32_t a1x = __float_as_uint(a1.x), a1y = __float_as_uint(a1.y),
                     a1z = __float_as_uint(a1.z), a1w = __float_as_uint(a1.w);

            mma_tf32(acc[0][0], a0x, a0y, a0z, a0w, __float_as_uint(bA.x), __float_as_uint(bA.y));
            mma_tf32(acc[1][0], a1x, a1y, a1z, a1w, __float_as_uint(bA.x), __float_as_uint(bA.y));
            mma_tf32(acc[0][1], a0x, a0y, a0z, a0w, __float_as_uint(bA.z), __float_as_uint(bA.w));
            mma_tf32(acc[1][1], a1x, a1y, a1z, a1w, __float_as_uint(bA.z), __float_as_uint(bA.w));
            mma_tf32(acc[0][2], a0x, a0y, a0z, a0w, __float_as_uint(bB.x), __float_as_uint(bB.y));
            mma_tf32(acc[1][2], a1x, a1y, a1z, a1w, __float_as_uint(bB.x), __float_as_uint(bB.y));
            mma_tf32(acc[0][3], a0x, a0y, a0z, a0w, __float_as_uint(bB.z), __float_as_uint(bB.w));
            mma_tf32(acc[1][3], a1x, a1y, a1z, a1w, __float_as_uint(bB.z), __float_as_uint(bB.w));

            if (q < 7) { a0 = na0; a1 = na1; bA = nbA; bB = nbB; }
        }
    }

    // ---- epilogue: route acc through smem (reuse stage memory), fused LSTM ----
    __syncthreads();
    float* Gs = smem;                       // [128][68]
    #pragma unroll
    for (int mi = 0; mi < 2; mi++) {
        #pragma unroll
        for (int ni = 0; ni < 4; ni++) {
            #pragma unroll
            for (int rh = 0; rh < 2; rh++) {
                int row = wm * 32 + mi * 16 + g + rh * 8;
                int col = wn * 32 + ni * 8 + 2 * tg;
                *reinterpret_cast<float2*>(&Gs[row * 68 + col]) =
                    make_float2(acc[mi][ni][rh * 2 + 0], acc[mi][ni][rh * 2 + 1]);
            }
        }
    }
    __syncthreads();

    const float* __restrict__ gih = g_Gih + ((size_t)(t * 128 + cta) * 128) * 64;
    const int n0 = cta * 16;

    #pragma unroll
    for (int p = 0; p < 8; p++) {
        int idx = p * 256 + tid;
        int c   = idx & 15;
        int b   = idx >> 4;
        const float* base = gih + b * 64;

        float iv = Gs[b * 68 +      c] + base[     c];
        float fv = Gs[b * 68 + 16 + c] + base[16 + c];
        float gv = Gs[b * 68 + 32 + c] + base[32 + c];
        float ov = Gs[b * 68 + 48 + c] + base[48 + c];

        float ig = sigmoidf_(iv);
        float fg = sigmoidf_(fv);
        float gg = tanhf(gv);
        float og = sigmoidf_(ov);

        int hcol = n0 + c;
        float cold = g_c[b * HH + hcol];
        float cn = fg * cold + ig * gg;
        g_c[b * HH + hcol] = cn;
        float hn = og * tanhf(cn);

        // packed store for the next step's A operand (tf32-rounded)
        int kc2   = hcol >> 6;
        int q2    = (hcol >> 3) & 7;
        int tg2   = hcol & 3;
        int khalf = (hcol >> 2) & 1;
        int mt    = b >> 4;
        int g2    = b & 7;
        int rh    = (b >> 3) & 1;
        int lane2 = g2 * 4 + tg2;
        int slot  = khalf * 2 + rh;
        h_out[((kc2 * 8 + q2) * 8 + mt) * 128 + lane2 * 4 + slot] = __uint_as_float(f2tf(hn));

        if (d_out_opt) d_out_opt[b * HH + hcol] = hn;
    }
}

// ---------------------------------------------------------------------------
extern "C" void kernel_launch(void* const* d_in, const int* in_sizes, int n_in,
                              void* d_out, int out_size) {
    (void)in_sizes; (void)n_in; (void)out_size;
    const int*   input = (const int*)  d_in[0];
    const float* embed = (const float*)d_in[1];
    const float* w_ih  = (const float*)d_in[2];
    const float* w_hh  = (const float*)d_in[3];
    const float* b_ih  = (const float*)d_in[4];
    const float* b_hh  = (const float*)d_in[5];
    float* out = (float*)d_out;

    static int smem_set = 0;
    if (!smem_set) {
        cudaFuncSetAttribute(step_kernel, cudaFuncAttributeMaxDynamicSharedMemorySize, SMEM_BYTES);
        smem_set = 1;
    }

    init_kernel<<<(BB * HH + 255) / 256, 256>>>();
    pack_w_kernel<<<16384, 256>>>(w_hh);
    phase1_kernel<<<dim3(64, 64), 256>>>(input, embed, w_ih, b_ih, b_hh);
    for (int t = 0; t < TT; t++) {
        step_kernel<<<128, 256, SMEM_BYTES>>>(t, (t == TT - 1) ? out : nullptr);
    }
}

// round 9
// speedup vs baseline: 2.0075x; 1.1230x over previous
#include <cuda_runtime.h>
#include <cstdint>
#include <cstddef>

// Problem dims
#define BB 128
#define TT 64
#define EE 300
#define HH 2048
#define G4 8192          // 4*H
#define TOK 8192         // T*B

// Packed-chunk geometry for the recurrent GEMM
#define CHUNK 64                     // K elements per pipeline stage
#define NCHUNK (HH / CHUNK)          // 32
#define A_CH_FLOATS (BB * CHUNK)     // 8192 floats per A chunk (32KB)
#define B_CH_FLOATS (64 * CHUNK)     // 4096 floats per B chunk (16KB)
#define STAGE_FLOATS (A_CH_FLOATS + B_CH_FLOATS)  // 12288
#define NSTAGE 4
#define SMEM_BYTES (NSTAGE * STAGE_FLOATS * 4)    // 196608

// Device scratch (allocation-free rule: static __device__ globals)
__device__ float g_Gih[(size_t)TOK * G4];            // 256 MB, layout ((t*128+cta)*128+b)*64 + gate*16 + c
__device__ float g_Wpack[(size_t)128 * NCHUNK * B_CH_FLOATS]; // 64 MB tf32-rounded, fragment-packed
__device__ float g_hpack[2][BB * HH];                // fragment-packed, tf32-rounded hidden state
__device__ float g_c[BB * HH];                       // cell state (fp32, plain [b][h])

// ---------------------------------------------------------------------------
__device__ __forceinline__ uint32_t f2tf(float f) {
    uint32_t u;
    asm("cvt.rna.tf32.f32 %0, %1;" : "=r"(u) : "f"(f));
    return u;
}

__device__ __forceinline__ void mma_tf32(float* d, uint32_t a0, uint32_t a1, uint32_t a2, uint32_t a3,
                                         uint32_t b0, uint32_t b1) {
    asm volatile(
        "mma.sync.aligned.m16n8k8.row.col.f32.tf32.tf32.f32 "
        "{%0,%1,%2,%3}, {%4,%5,%6,%7}, {%8,%9}, {%0,%1,%2,%3};\n"
        : "+f"(d[0]), "+f"(d[1]), "+f"(d[2]), "+f"(d[3])
        : "r"(a0), "r"(a1), "r"(a2), "r"(a3), "r"(b0), "r"(b1));
}

__device__ __forceinline__ void cp16(float* s, const float* g) {
    uint32_t sa = (uint32_t)__cvta_generic_to_shared(s);
    asm volatile("cp.async.cg.shared.global [%0], [%1], 16;\n" :: "r"(sa), "l"(g));
}
#define CP_COMMIT() asm volatile("cp.async.commit_group;\n" ::: "memory")
#define CP_WAIT(N)  asm volatile("cp.async.wait_group %0;\n" :: "n"(N) : "memory")

__device__ __forceinline__ float sigmoidf_(float x) {
    return 1.0f / (1.0f + __expf(-x));
}

// ---------------------------------------------------------------------------
// init: zero h0 (packed) and c0
// ---------------------------------------------------------------------------
__global__ void init_kernel() {
    int i = blockIdx.x * blockDim.x + threadIdx.x;
    if (i < BB * HH) {
        g_hpack[0][i] = 0.0f;
        g_c[i]        = 0.0f;
    }
}

// ---------------------------------------------------------------------------
// Pack W_hh into tf32-rounded, B-fragment order.
// Layout: [cta 128][kc 32][q 8][pair 4][lane 32][slot 4]
// ---------------------------------------------------------------------------
__global__ __launch_bounds__(256) void pack_w_kernel(const float* __restrict__ w_hh) {
    int p4 = blockIdx.x * blockDim.x + threadIdx.x;   // 0 .. 4194303
    int lane = p4 & 31;  int rest = p4 >> 5;
    int pair = rest & 3; rest >>= 2;
    int q    = rest & 7; rest >>= 3;
    int kc   = rest & 31;
    int cta  = rest >> 5;
    int g  = lane >> 2;
    int tg = lane & 3;

    float4 v;
    float* vv = (float*)&v;
    #pragma unroll
    for (int which = 0; which < 2; which++) {
        int j = (pair * 2 + which) * 8 + g;
        int wrow = (j >> 4) * HH + cta * 16 + (j & 15);
        #pragma unroll
        for (int khalf = 0; khalf < 2; khalf++) {
            int k = kc * CHUNK + q * 8 + khalf * 4 + tg;
            float x = w_hh[(size_t)wrow * HH + k];
            vv[which * 2 + khalf] = __uint_as_float(f2tf(x));
        }
    }
    *reinterpret_cast<float4*>(&g_Wpack[(size_t)p4 * 4]) = v;
}

// ---------------------------------------------------------------------------
// Phase 1: G_ih[r][N] = embed[input[r]] @ W_ih^T + b_ih + b_hh
// ---------------------------------------------------------------------------
__global__ __launch_bounds__(256) void phase1_kernel(
    const int*   __restrict__ input,
    const float* __restrict__ embed,
    const float* __restrict__ w_ih,
    const float* __restrict__ b_ih,
    const float* __restrict__ b_hh)
{
    __shared__ float sbuf[9216];   // As: 128x36, Bs: 128x36
    __shared__ int   ids[128];
    float* As = sbuf;
    float* Bs = sbuf + 4608;

    const int tid  = threadIdx.x;
    const int lane = tid & 31;
    const int warp = tid >> 5;
    const int wm   = warp >> 1;
    const int wn   = warp & 1;
    const int g    = lane >> 2;
    const int tg   = lane & 3;

    const int n0 = blockIdx.x * 128;
    const int r0 = blockIdx.y * 128;

    if (tid < 128) {
        int r = r0 + tid;
        int b = r & 127;
        int t = r >> 7;
        ids[tid] = input[b * TT + t];
    }

    float acc[2][8][4];
    #pragma unroll
    for (int mi = 0; mi < 2; mi++)
        #pragma unroll
        for (int ni = 0; ni < 8; ni++)
            #pragma unroll
            for (int e = 0; e < 4; e++) acc[mi][ni][e] = 0.0f;

    for (int kc = 0; kc < 320; kc += 32) {
        __syncthreads();
        #pragma unroll
        for (int p = 0; p < 4; p++) {
            int v   = p * 256 + tid;
            int row = v >> 3;
            int k4  = (v & 7) * 4;
            int kk  = kc + k4;
            float4 val = make_float4(0.f, 0.f, 0.f, 0.f);
            if (kk <= 296) {
                val = *reinterpret_cast<const float4*>(embed + (size_t)ids[row] * EE + kk);
            }
            *reinterpret_cast<float4*>(&As[row * 36 + k4]) = val;
        }
        #pragma unroll
        for (int p = 0; p < 4; p++) {
            int v   = p * 256 + tid;
            int row = v >> 3;
            int k4  = (v & 7) * 4;
            int kk  = kc + k4;
            float4 val = make_float4(0.f, 0.f, 0.f, 0.f);
            if (kk <= 296) {
                val = *reinterpret_cast<const float4*>(w_ih + (size_t)(n0 + row) * EE + kk);
            }
            *reinterpret_cast<float4*>(&Bs[row * 36 + k4]) = val;
        }
        __syncthreads();

        #pragma unroll
        for (int q = 0; q < 4; q++) {
            int kq = q * 8;
            uint32_t af[2][4];
            #pragma unroll
            for (int mi = 0; mi < 2; mi++) {
                int rb = wm * 32 + mi * 16;
                af[mi][0] = f2tf(As[(rb + g    ) * 36 + kq + tg    ]);
                af[mi][1] = f2tf(As[(rb + g + 8) * 36 + kq + tg    ]);
                af[mi][2] = f2tf(As[(rb + g    ) * 36 + kq + tg + 4]);
                af[mi][3] = f2tf(As[(rb + g + 8) * 36 + kq + tg + 4]);
            }
            uint32_t bf[8][2];
            #pragma unroll
            for (int ni = 0; ni < 8; ni++) {
                int cb = wn * 64 + ni * 8;
                bf[ni][0] = f2tf(Bs[(cb + g) * 36 + kq + tg    ]);
                bf[ni][1] = f2tf(Bs[(cb + g) * 36 + kq + tg + 4]);
            }
            #pragma unroll
            for (int mi = 0; mi < 2; mi++)
                #pragma unroll
                for (int ni = 0; ni < 8; ni++)
                    mma_tf32(acc[mi][ni], af[mi][0], af[mi][1], af[mi][2], af[mi][3],
                             bf[ni][0], bf[ni][1]);
        }
    }

    #pragma unroll
    for (int mi = 0; mi < 2; mi++) {
        #pragma unroll
        for (int ni = 0; ni < 8; ni++) {
            #pragma unroll
            for (int h2 = 0; h2 < 2; h2++) {
                int row = r0 + wm * 32 + mi * 16 + g + h2 * 8;
                int t = row >> 7;
                int b = row & 127;
                int col = n0 + wn * 64 + ni * 8 + 2 * tg;
                int cta = (col & (HH - 1)) >> 4;
                int j   = (col >> 11) * 16 + (col & 15);
                float v0 = acc[mi][ni][h2 * 2 + 0] + b_ih[col]     + b_hh[col];
                float v1 = acc[mi][ni][h2 * 2 + 1] + b_ih[col + 1] + b_hh[col + 1];
                size_t addr = ((size_t)(t * 128 + cta) * 128 + b) * 64 + j;
                *reinterpret_cast<float2*>(&g_Gih[addr]) = make_float2(v0, v1);
            }
        }
    }
}

// ---------------------------------------------------------------------------
// Step t: gates = G_ih[t] + h @ W_hh^T ; fused LSTM cell update.
// 128 CTAs, 512 threads = 16 warps as 4(M) x 2(N) x 2(K-slice).
// Each warp: 32x32 tile over half the K-chunk (4 of 8 q iterations).
// Cross-slice reduction via two smem accumulator images in the epilogue.
// ---------------------------------------------------------------------------
__global__ __launch_bounds__(512) void step_kernel(int t, float* __restrict__ d_out_opt)
{
    extern __shared__ float smem[];

    const float* __restrict__ h_in  = g_hpack[t & 1];
    float*       __restrict__ h_out = g_hpack[(t + 1) & 1];

    const int tid  = threadIdx.x;
    const int lane = tid & 31;
    const int warp = tid >> 5;      // 0..15
    const int wm   = warp >> 2;     // 0..3  (M)
    const int wn   = (warp >> 1) & 1; // 0..1 (N)
    const int wk   = warp & 1;      // 0..1  (K slice)
    const int g    = lane >> 2;
    const int tg   = lane & 3;
    const int cta  = blockIdx.x;

    const float* __restrict__ wb = g_Wpack + (size_t)cta * (NCHUNK * B_CH_FLOATS);

    auto load_stage = [&](int s, int kc) {
        float* dst = smem + s * STAGE_FLOATS;
        const float* ga = h_in + (size_t)kc * A_CH_FLOATS;
        const float* gb = wb + (size_t)kc * B_CH_FLOATS;
        #pragma unroll
        for (int i = 0; i < A_CH_FLOATS / (512 * 4); i++)   // 4
            cp16(dst + (i * 512 + tid) * 4, ga + (i * 512 + tid) * 4);
        #pragma unroll
        for (int i = 0; i < B_CH_FLOATS / (512 * 4); i++)   // 2
            cp16(dst + A_CH_FLOATS + (i * 512 + tid) * 4, gb + (i * 512 + tid) * 4);
    };

    load_stage(0, 0); CP_COMMIT();
    load_stage(1, 1); CP_COMMIT();
    load_stage(2, 2); CP_COMMIT();

    float acc[2][4][4];
    #pragma unroll
    for (int mi = 0; mi < 2; mi++)
        #pragma unroll
        for (int ni = 0; ni < 4; ni++)
            #pragma unroll
            for (int e = 0; e < 4; e++) acc[mi][ni][e] = 0.0f;

    for (int kc = 0; kc < NCHUNK; kc++) {
        CP_WAIT(2);
        __syncthreads();
        if (kc + 3 < NCHUNK) load_stage((kc + 3) & 3, kc + 3);
        CP_COMMIT();

        const float* S = smem + (kc & 3) * STAGE_FLOATS;
        const float* SA = S + lane * 4;
        const float* SB = S + A_CH_FLOATS + lane * 4;

        #pragma unroll
        for (int qq = 0; qq < 4; qq++) {
            int q = wk * 4 + qq;
            float4 a0 = *reinterpret_cast<const float4*>(SA + (q * 8 + wm * 2 + 0) * 128);
            float4 a1 = *reinterpret_cast<const float4*>(SA + (q * 8 + wm * 2 + 1) * 128);
            float4 bA = *reinterpret_cast<const float4*>(SB + (q * 4 + wn * 2 + 0) * 128);
            float4 bB = *reinterpret_cast<const float4*>(SB + (q * 4 + wn * 2 + 1) * 128);

            uint32_t a0x = __float_as_uint(a0.x), a0y = __float_as_uint(a0.y),
                     a0z = __float_as_uint(a0.z), a0w = __float_as_uint(a0.w);
            uint32_t a1x = __float_as_uint(a1.x), a1y = __float_as_uint(a1.y),
                     a1z = __float_as_uint(a1.z), a1w = __float_as_uint(a1.w);

            mma_tf32(acc[0][0], a0x, a0y, a0z, a0w, __float_as_uint(bA.x), __float_as_uint(bA.y));
            mma_tf32(acc[1][0], a1x, a1y, a1z, a1w, __float_as_uint(bA.x), __float_as_uint(bA.y));
            mma_tf32(acc[0][1], a0x, a0y, a0z, a0w, __float_as_uint(bA.z), __float_as_uint(bA.w));
            mma_tf32(acc[1][1], a1x, a1y, a1z, a1w, __float_as_uint(bA.z), __float_as_uint(bA.w));
            mma_tf32(acc[0][2], a0x, a0y, a0z, a0w, __float_as_uint(bB.x), __float_as_uint(bB.y));
            mma_tf32(acc[1][2], a1x, a1y, a1z, a1w, __float_as_uint(bB.x), __float_as_uint(bB.y));
            mma_tf32(acc[0][3], a0x, a0y, a0z, a0w, __float_as_uint(bB.z), __float_as_uint(bB.w));
            mma_tf32(acc[1][3], a1x, a1y, a1z, a1w, __float_as_uint(bB.z), __float_as_uint(bB.w));
        }
    }

    // ---- epilogue: both K-slices dump accumulators to smem, then fuse ----
    __syncthreads();
    float* Gb = smem + wk * 8704;           // two [128][68] images
    #pragma unroll
    for (int mi = 0; mi < 2; mi++) {
        #pragma unroll
        for (int ni = 0; ni < 4; ni++) {
            #pragma unroll
            for (int rh = 0; rh < 2; rh++) {
                int row = wm * 32 + mi * 16 + g + rh * 8;
                int col = wn * 32 + ni * 8 + 2 * tg;
                *reinterpret_cast<float2*>(&Gb[row * 68 + col]) =
                    make_float2(acc[mi][ni][rh * 2 + 0], acc[mi][ni][rh * 2 + 1]);
            }
        }
    }
    __syncthreads();

    const float* __restrict__ G0 = smem;
    const float* __restrict__ G1 = smem + 8704;
    const float* __restrict__ gih = g_Gih + ((size_t)(t * 128 + cta) * 128) * 64;
    const int n0 = cta * 16;

    #pragma unroll
    for (int p = 0; p < 4; p++) {
        int idx = p * 512 + tid;
        int c   = idx & 15;
        int b   = idx >> 4;
        const float* base = gih + b * 64;

        float iv = G0[b * 68 +      c] + G1[b * 68 +      c] + base[     c];
        float fv = G0[b * 68 + 16 + c] + G1[b * 68 + 16 + c] + base[16 + c];
        float gv = G0[b * 68 + 32 + c] + G1[b * 68 + 32 + c] + base[32 + c];
        float ov = G0[b * 68 + 48 + c] + G1[b * 68 + 48 + c] + base[48 + c];

        float ig = sigmoidf_(iv);
        float fg = sigmoidf_(fv);
        float gg = tanhf(gv);
        float og = sigmoidf_(ov);

        int hcol = n0 + c;
        float cold = g_c[b * HH + hcol];
        float cn = fg * cold + ig * gg;
        g_c[b * HH + hcol] = cn;
        float hn = og * tanhf(cn);

        // packed store for the next step's A operand (tf32-rounded)
        int kc2   = hcol >> 6;
        int q2    = (hcol >> 3) & 7;
        int tg2   = hcol & 3;
        int khalf = (hcol >> 2) & 1;
        int mt    = b >> 4;
        int g2    = b & 7;
        int rh    = (b >> 3) & 1;
        int lane2 = g2 * 4 + tg2;
        int slot  = khalf * 2 + rh;
        h_out[((kc2 * 8 + q2) * 8 + mt) * 128 + lane2 * 4 + slot] = __uint_as_float(f2tf(hn));

        if (d_out_opt) d_out_opt[b * HH + hcol] = hn;
    }
}

// ---------------------------------------------------------------------------
extern "C" void kernel_launch(void* const* d_in, const int* in_sizes, int n_in,
                              void* d_out, int out_size) {
    (void)in_sizes; (void)n_in; (void)out_size;
    const int*   input = (const int*)  d_in[0];
    const float* embed = (const float*)d_in[1];
    const float* w_ih  = (const float*)d_in[2];
    const float* w_hh  = (const float*)d_in[3];
    const float* b_ih  = (const float*)d_in[4];
    const float* b_hh  = (const float*)d_in[5];
    float* out = (float*)d_out;

    static int smem_set = 0;
    if (!smem_set) {
        cudaFuncSetAttribute(step_kernel, cudaFuncAttributeMaxDynamicSharedMemorySize, SMEM_BYTES);
        smem_set = 1;
    }

    init_kernel<<<(BB * HH + 255) / 256, 256>>>();
    pack_w_kernel<<<16384, 256>>>(w_hh);
    phase1_kernel<<<dim3(64, 64), 256>>>(input, embed, w_ih, b_ih, b_hh);
    for (int t = 0; t < TT; t++) {
        step_kernel<<<128, 512, SMEM_BYTES>>>(t, (t == TT - 1) ? out : nullptr);
    }
}